// round 1
// baseline (speedup 1.0000x reference)
#include <cuda_runtime.h>
#include <cstdint>

typedef unsigned long long u64;

// ---- packed f32x2 helpers (Blackwell sm_100+; FFMA2 only reachable via PTX) ----
__device__ __forceinline__ u64 pack2(float lo, float hi) {
    u64 r; asm("mov.b64 %0, {%1, %2};" : "=l"(r) : "f"(lo), "f"(hi)); return r;
}
__device__ __forceinline__ void unpack2(u64 v, float& lo, float& hi) {
    asm("mov.b64 {%0, %1}, %2;" : "=f"(lo), "=f"(hi) : "l"(v));
}
__device__ __forceinline__ u64 sub2(u64 a, u64 b) {
    u64 r; asm("sub.rn.f32x2 %0, %1, %2;" : "=l"(r) : "l"(a), "l"(b)); return r;
}
__device__ __forceinline__ u64 fma2(u64 a, u64 b, u64 c) {
    u64 r; asm("fma.rn.f32x2 %0, %1, %2, %3;" : "=l"(r) : "l"(a), "l"(b), "l"(c)); return r;
}

#define L_PATH 256
#define D_CH   8
#define OUT_B  584   // 8 + 64 + 512

// One warp per batch element.
// Lane l owns pairs p = 2l, 2l+1:  i = l>>2 (same for both), j = j0, j0+1 with j0 = (l&3)*2.
// State per lane: S1_i scalar, S2 pair packed, S3 = 16 floats as 8 f32x2 regs.
__global__ void __launch_bounds__(256)
logsig_kernel(const float* __restrict__ x, float* __restrict__ out, int B)
{
    __shared__ float sS2[8][64];
    __shared__ float sS1[8][8];

    const int wib  = threadIdx.x >> 5;
    const int lane = threadIdx.x & 31;
    const int warp = blockIdx.x * 8 + wib;
    if (warp >= B) return;

    const float* __restrict__ xb = x + (size_t)warp * (L_PATH * D_CH);

    const int i  = lane >> 2;
    const int j0 = (lane & 3) << 1;

    // first row: x0 (kept to reconstruct full S1 at the end)
    ulonglong2 r0 = *reinterpret_cast<const ulonglong2*>(xb);
    ulonglong2 r1 = *reinterpret_cast<const ulonglong2*>(xb + 4);
    u64 x0p0 = r0.x, x0p1 = r0.y, x0p2 = r1.x, x0p3 = r1.y;
    u64 xpp0 = r0.x, xpp1 = r0.y, xpp2 = r1.x, xpp3 = r1.y;
    float xpi = __ldg(xb + i);
    u64 xpj;
    { float2 fj = *reinterpret_cast<const float2*>(xb + j0); xpj = pack2(fj.x, fj.y); }

    float S1i = 0.0f;        // S1[i] only — full S1 = x_last - x0 reconstructed later
    u64 S2p   = 0ull;        // (S2[i,j0], S2[i,j1]) packed; bit pattern 0 == (0.f,0.f)
    u64 S30[4] = {0ull,0ull,0ull,0ull};   // S3[p=2l ][k], k-pairs packed
    u64 S31[4] = {0ull,0ull,0ull,0ull};   // S3[p=2l+1][k]

    #pragma unroll 2
    for (int t = 1; t < L_PATH; ++t) {
        const float* row = xb + t * D_CH;
        ulonglong2 c0 = *reinterpret_cast<const ulonglong2*>(row);
        ulonglong2 c1 = *reinterpret_cast<const ulonglong2*>(row + 4);
        float xci = __ldg(row + i);                 // scalar: avoids dynamic reg-array index
        u64 xcj;
        { float2 fj = *reinterpret_cast<const float2*>(row + j0); xcj = pack2(fj.x, fj.y); }

        // increments
        u64 dx0 = sub2(c0.x, xpp0);
        u64 dx1 = sub2(c0.y, xpp1);
        u64 dx2 = sub2(c1.x, xpp2);
        u64 dx3 = sub2(c1.y, xpp3);
        float dxi = xci - xpi;
        u64   dxj = sub2(xcj, xpj);

        // level-3 update collapses to rank-1:
        //   t_p = S2_old[p] + 0.5*dx_j*(S1_i + dx_i/3);  S3[p,k] += t_p * dx_k
        float g = fmaf(dxi, (1.0f/3.0f), S1i);
        float c = 0.5f * g;
        u64 tq = fma2(pack2(c, c), dxj, S2p);
        float t0, t1; unpack2(tq, t0, t1);
        u64 t0p = pack2(t0, t0);
        u64 t1p = pack2(t1, t1);
        S30[0] = fma2(t0p, dx0, S30[0]);
        S30[1] = fma2(t0p, dx1, S30[1]);
        S30[2] = fma2(t0p, dx2, S30[2]);
        S30[3] = fma2(t0p, dx3, S30[3]);
        S31[0] = fma2(t1p, dx0, S31[0]);
        S31[1] = fma2(t1p, dx1, S31[1]);
        S31[2] = fma2(t1p, dx2, S31[2]);
        S31[3] = fma2(t1p, dx3, S31[3]);

        // level-2: S2[p] += (S1_i + 0.5*dx_i) * dx_j
        float a = fmaf(dxi, 0.5f, S1i);
        S2p = fma2(pack2(a, a), dxj, S2p);
        S1i += dxi;

        xpp0 = c0.x; xpp1 = c0.y; xpp2 = c1.x; xpp3 = c1.y;
        xpi = xci; xpj = xcj;
    }

    // ======================= epilogue: log() + write =======================
    float S1[8];
    unpack2(sub2(xpp0, x0p0), S1[0], S1[1]);
    unpack2(sub2(xpp1, x0p1), S1[2], S1[3]);
    unpack2(sub2(xpp2, x0p2), S1[4], S1[5]);
    unpack2(sub2(xpp3, x0p3), S1[6], S1[7]);
    float S2a, S2b; unpack2(S2p, S2a, S2b);

    // publish S1 (predicated static stores keep indices compile-time) and S2 to smem
    #pragma unroll
    for (int k = 0; k < 8; ++k) if (lane == k) sS1[wib][k] = S1[k];
    sS2[wib][2*lane]     = S2a;
    sS2[wib][2*lane + 1] = S2b;
    __syncwarp();

    const float s1i  = sS1[wib][i];
    const float s1j0 = sS1[wib][j0];
    const float s1j1 = sS1[wib][j0 + 1];

    float* ob = out + (size_t)warp * OUT_B;

    // level 1: l1 = S1
    if (lane < 8) ob[lane] = sS1[wib][lane];

    // level 2: l2[i,j] = S2[i,j] - 0.5*S1_i*S1_j   (2 contiguous floats per lane)
    float l2a = fmaf(-0.5f * s1i, s1j0, S2a);
    float l2b = fmaf(-0.5f * s1i, s1j1, S2b);
    *reinterpret_cast<float2*>(ob + 8 + 2*lane) = make_float2(l2a, l2b);

    // level 3:
    // l3[i,j,k] = S3 - 0.5*S1_i*S2[j,k] + (-0.5*S2[i,j] + (1/3)*S1_i*S1_j) * S1_k
    const float h  = -0.5f * s1i;
    const float e0 = (1.0f/3.0f) * s1i * s1j0 - 0.5f * S2a;
    const float e1 = (1.0f/3.0f) * s1i * s1j1 - 0.5f * S2b;

    float l3[16];
    #pragma unroll
    for (int kk = 0; kk < 4; ++kk) {
        float s3a, s3b; unpack2(S30[kk], s3a, s3b);
        int k0 = 2*kk;
        l3[k0]     = s3a + h * sS2[wib][j0*8 + k0]     + e0 * S1[k0];
        l3[k0 + 1] = s3b + h * sS2[wib][j0*8 + k0 + 1] + e0 * S1[k0 + 1];
    }
    #pragma unroll
    for (int kk = 0; kk < 4; ++kk) {
        float s3a, s3b; unpack2(S31[kk], s3a, s3b);
        int k0 = 2*kk;
        l3[8 + k0]     = s3a + h * sS2[wib][(j0+1)*8 + k0]     + e1 * S1[k0];
        l3[8 + k0 + 1] = s3b + h * sS2[wib][(j0+1)*8 + k0 + 1] + e1 * S1[k0 + 1];
    }

    // lane's 16 l3 coefficients are contiguous: out index 72 + 16*lane (+8q+k)
    float* o3 = ob + 72 + 16*lane;
    #pragma unroll
    for (int v = 0; v < 4; ++v)
        *reinterpret_cast<float4*>(o3 + 4*v) =
            make_float4(l3[4*v], l3[4*v+1], l3[4*v+2], l3[4*v+3]);
}

extern "C" void kernel_launch(void* const* d_in, const int* in_sizes, int n_in,
                              void* d_out, int out_size)
{
    const float* x = (const float*)d_in[0];
    float* out = (float*)d_out;
    const int B = in_sizes[0] / (L_PATH * D_CH);   // 2048 for the given shapes
    const int blocks = (B + 7) / 8;                // 8 warps (batch elements) per block
    logsig_kernel<<<blocks, 256>>>(x, out, B);
}

// round 2
// speedup vs baseline: 1.5476x; 1.5476x over previous
#include <cuda_runtime.h>
#include <cstdint>

typedef unsigned long long u64;

// ---- packed f32x2 helpers (Blackwell sm_100+; FFMA2 only reachable via PTX) ----
__device__ __forceinline__ u64 pack2(float lo, float hi) {
    u64 r; asm("mov.b64 %0, {%1, %2};" : "=l"(r) : "f"(lo), "f"(hi)); return r;
}
__device__ __forceinline__ void unpack2(u64 v, float& lo, float& hi) {
    asm("mov.b64 {%0, %1}, %2;" : "=f"(lo), "=f"(hi) : "l"(v));
}
__device__ __forceinline__ u64 sub2(u64 a, u64 b) {
    u64 r; asm("sub.rn.f32x2 %0, %1, %2;" : "=l"(r) : "l"(a), "l"(b)); return r;
}
__device__ __forceinline__ u64 add2(u64 a, u64 b) {
    u64 r; asm("add.rn.f32x2 %0, %1, %2;" : "=l"(r) : "l"(a), "l"(b)); return r;
}
__device__ __forceinline__ u64 fma2(u64 a, u64 b, u64 c) {
    u64 r; asm("fma.rn.f32x2 %0, %1, %2, %3;" : "=l"(r) : "l"(a), "l"(b), "l"(c)); return r;
}

#define L_PATH 256
#define D_CH   8
#define OUT_B  584   // 8 + 64 + 512
#define SLOT   584   // floats per signature slot: S1 @0, S2 @8 (row-major [i][j]), S3 @72 ([p][k], p=8i+j)

// Chen combine: (A <- A (x) B), B read from a shared-memory slot.
// Lane layout: i = lane>>2, j0 = (lane&3)*2; lane owns S2[i,j0..j0+1] and
// S3 rows p0=2*lane (i,j0) and p1=2*lane+1 (i,j1), 8 k-values each (packed f32x2).
__device__ __forceinline__ void chen_combine(
    const float* __restrict__ s, int lane, int i, int j0,
    u64 S30[4], u64 S31[4], u64& S2p, u64 S1p[4], float& S1ai)
{
    float S2a0, S2a1; unpack2(S2p, S2a0, S2a1);
    const u64 S2a0p = pack2(S2a0, S2a0);
    const u64 S2a1p = pack2(S2a1, S2a1);
    const u64 S1aip = pack2(S1ai, S1ai);

    ulonglong2 t0 = *reinterpret_cast<const ulonglong2*>(s);
    ulonglong2 t1 = *reinterpret_cast<const ulonglong2*>(s + 4);
    u64 S1bp[4] = {t0.x, t0.y, t1.x, t1.y};

    const float* rj = s + 8 + j0 * 8;
    ulonglong2 u0 = *reinterpret_cast<const ulonglong2*>(rj);
    ulonglong2 u1 = *reinterpret_cast<const ulonglong2*>(rj + 4);
    ulonglong2 v0 = *reinterpret_cast<const ulonglong2*>(rj + 8);
    ulonglong2 v1 = *reinterpret_cast<const ulonglong2*>(rj + 12);
    u64 Bj0[4] = {u0.x, u0.y, u1.x, u1.y};
    u64 Bj1[4] = {v0.x, v0.y, v1.x, v1.y};

    float2 s2bi = *reinterpret_cast<const float2*>(s + 8 + i * 8 + j0);
    float2 s1bj = *reinterpret_cast<const float2*>(s + j0);
    float  s1bi = s[i];

    const float* q = s + 72 + 16 * lane;
    ulonglong2 q0 = *reinterpret_cast<const ulonglong2*>(q);
    ulonglong2 q1 = *reinterpret_cast<const ulonglong2*>(q + 4);
    ulonglong2 q2 = *reinterpret_cast<const ulonglong2*>(q + 8);
    ulonglong2 q3 = *reinterpret_cast<const ulonglong2*>(q + 12);
    u64 Q0[4] = {q0.x, q0.y, q1.x, q1.y};
    u64 Q1[4] = {q2.x, q2.y, q3.x, q3.y};

    // S3 = S3a + S3b + S2a (x) S1b + S1a (x) S2b   (uses pre-update S2a, S1a)
    #pragma unroll
    for (int kk = 0; kk < 4; ++kk) {
        S30[kk] = add2(S30[kk], Q0[kk]);
        S30[kk] = fma2(S2a0p, S1bp[kk], S30[kk]);
        S30[kk] = fma2(S1aip, Bj0[kk], S30[kk]);
        S31[kk] = add2(S31[kk], Q1[kk]);
        S31[kk] = fma2(S2a1p, S1bp[kk], S31[kk]);
        S31[kk] = fma2(S1aip, Bj1[kk], S31[kk]);
    }
    // S2 = S2a + S2b + S1a (x) S1b
    S2p = add2(S2p, pack2(s2bi.x, s2bi.y));
    S2p = fma2(S1aip, pack2(s1bj.x, s1bj.y), S2p);
    // S1 = S1a + S1b
    #pragma unroll
    for (int kk = 0; kk < 4; ++kk) S1p[kk] = add2(S1p[kk], S1bp[kk]);
    S1ai += s1bi;
}

__device__ __forceinline__ void write_sig(
    float* __restrict__ s, int lane,
    const u64 S30[4], const u64 S31[4], u64 S2p, const u64 S1p[4])
{
    if (lane == 0) {
        *reinterpret_cast<ulonglong2*>(s)     = make_ulonglong2(S1p[0], S1p[1]);
        *reinterpret_cast<ulonglong2*>(s + 4) = make_ulonglong2(S1p[2], S1p[3]);
    }
    *reinterpret_cast<u64*>(s + 8 + 2 * lane) = S2p;
    float* q = s + 72 + 16 * lane;
    *reinterpret_cast<ulonglong2*>(q)      = make_ulonglong2(S30[0], S30[1]);
    *reinterpret_cast<ulonglong2*>(q + 4)  = make_ulonglong2(S30[2], S30[3]);
    *reinterpret_cast<ulonglong2*>(q + 8)  = make_ulonglong2(S31[0], S31[1]);
    *reinterpret_cast<ulonglong2*>(q + 12) = make_ulonglong2(S31[2], S31[3]);
}

// 256 threads = 8 warps = 2 batch elements x 4 chunks.
__global__ void __launch_bounds__(256, 4)
logsig_kernel(const float* __restrict__ x, float* __restrict__ out, int B)
{
    __shared__ float sig[2][4][SLOT];   // 18688 B

    const int wib   = threadIdx.x >> 5;
    const int lane  = threadIdx.x & 31;
    const int bloc  = wib >> 2;          // batch element within block
    const int chunk = wib & 3;
    const int batch = blockIdx.x * 2 + bloc;

    const int i  = lane >> 2;
    const int j0 = (lane & 3) << 1;

    const int base   = chunk * 64;
    const int nsteps = (chunk == 3) ? 63 : 64;
    const float* __restrict__ xb = x + (size_t)batch * (L_PATH * D_CH) + base * D_CH;

    // =================== chunk signature (Chen recursion) ===================
    ulonglong2 r0 = *reinterpret_cast<const ulonglong2*>(xb);
    ulonglong2 r1 = *reinterpret_cast<const ulonglong2*>(xb + 4);
    u64 x0p0 = r0.x, x0p1 = r0.y, x0p2 = r1.x, x0p3 = r1.y;
    u64 xpp0 = r0.x, xpp1 = r0.y, xpp2 = r1.x, xpp3 = r1.y;
    float xpi = xb[i];
    u64 xpj;
    { float2 fj = *reinterpret_cast<const float2*>(xb + j0); xpj = pack2(fj.x, fj.y); }

    float S1i = 0.0f;                       // running S1[i]
    u64 S2p   = 0ull;                       // (S2[i,j0], S2[i,j1])
    u64 S30[4] = {0ull,0ull,0ull,0ull};     // S3[p0][k] pairs
    u64 S31[4] = {0ull,0ull,0ull,0ull};     // S3[p1][k] pairs

    #pragma unroll 2
    for (int t = 1; t <= nsteps; ++t) {
        const float* row = xb + t * D_CH;
        ulonglong2 c0 = *reinterpret_cast<const ulonglong2*>(row);
        ulonglong2 c1 = *reinterpret_cast<const ulonglong2*>(row + 4);
        float xci = row[i];
        u64 xcj;
        { float2 fj = *reinterpret_cast<const float2*>(row + j0); xcj = pack2(fj.x, fj.y); }

        u64 dx0 = sub2(c0.x, xpp0);
        u64 dx1 = sub2(c0.y, xpp1);
        u64 dx2 = sub2(c1.x, xpp2);
        u64 dx3 = sub2(c1.y, xpp3);
        float dxi = xci - xpi;
        u64   dxj = sub2(xcj, xpj);

        // level-3 rank-1 update: t_p = S2[p] + 0.5*dx_j*(S1_i + dx_i/3); S3[p,k] += t_p*dx_k
        float g = fmaf(dxi, (1.0f/3.0f), S1i);
        float c = 0.5f * g;
        u64 tq = fma2(pack2(c, c), dxj, S2p);
        float t0, t1; unpack2(tq, t0, t1);
        u64 t0p = pack2(t0, t0);
        u64 t1p = pack2(t1, t1);
        S30[0] = fma2(t0p, dx0, S30[0]);
        S30[1] = fma2(t0p, dx1, S30[1]);
        S30[2] = fma2(t0p, dx2, S30[2]);
        S30[3] = fma2(t0p, dx3, S30[3]);
        S31[0] = fma2(t1p, dx0, S31[0]);
        S31[1] = fma2(t1p, dx1, S31[1]);
        S31[2] = fma2(t1p, dx2, S31[2]);
        S31[3] = fma2(t1p, dx3, S31[3]);

        // level-2: S2[p] += (S1_i + 0.5*dx_i)*dx_j
        float a = fmaf(dxi, 0.5f, S1i);
        S2p = fma2(pack2(a, a), dxj, S2p);
        S1i += dxi;

        xpp0 = c0.x; xpp1 = c0.y; xpp2 = c1.x; xpp3 = c1.y;
        xpi = xci; xpj = xcj;
    }

    // chunk S1 (all 8 channels, packed)
    u64 S1p[4];
    S1p[0] = sub2(xpp0, x0p0);
    S1p[1] = sub2(xpp1, x0p1);
    S1p[2] = sub2(xpp2, x0p2);
    S1p[3] = sub2(xpp3, x0p3);

    // ===================== tree combine via shared memory ===================
    float* myslot = &sig[bloc][chunk][0];

    if (chunk & 1)                      // chunks 1 and 3 publish
        write_sig(myslot, lane, S30, S31, S2p, S1p);
    __syncthreads();

    if (!(chunk & 1))                   // warp0: 0(x)1, warp2: 2(x)3
        chen_combine(&sig[bloc][chunk + 1][0], lane, i, j0, S30, S31, S2p, S1p, S1i);
    if (chunk == 2)                     // publish combined right half
        write_sig(myslot, lane, S30, S31, S2p, S1p);
    __syncthreads();

    if (chunk != 0) return;

    chen_combine(&sig[bloc][2][0], lane, i, j0, S30, S31, S2p, S1p, S1i);

    // ======================= epilogue: log() + write =======================
    float S1[8];
    unpack2(S1p[0], S1[0], S1[1]);
    unpack2(S1p[1], S1[2], S1[3]);
    unpack2(S1p[2], S1[4], S1[5]);
    unpack2(S1p[3], S1[6], S1[7]);
    float S2a, S2b; unpack2(S2p, S2a, S2b);

    // publish final S1 + S2 grid to slot 0 for cross-lane reads
    float* s0 = &sig[bloc][0][0];
    if (lane == 0) {
        *reinterpret_cast<ulonglong2*>(s0)     = make_ulonglong2(S1p[0], S1p[1]);
        *reinterpret_cast<ulonglong2*>(s0 + 4) = make_ulonglong2(S1p[2], S1p[3]);
    }
    *reinterpret_cast<u64*>(s0 + 8 + 2 * lane) = S2p;
    __syncwarp();

    const float s1i  = S1i;            // == S1[i], tracked through combines
    float2 s1j = *reinterpret_cast<const float2*>(s0 + j0);
    const float s1j0 = s1j.x, s1j1 = s1j.y;

    float* ob = out + (size_t)batch * OUT_B;

    // level 1
    if (lane < 8) ob[lane] = s0[lane];

    // level 2: l2 = S2 - 0.5*S1 (x) S1
    float l2a = fmaf(-0.5f * s1i, s1j0, S2a);
    float l2b = fmaf(-0.5f * s1i, s1j1, S2b);
    *reinterpret_cast<float2*>(ob + 8 + 2 * lane) = make_float2(l2a, l2b);

    // level 3: l3 = S3 - 0.5*(S1 (x) S2 + S2 (x) S1) + (1/3) S1 (x) S1 (x) S1
    const float h  = -0.5f * s1i;
    const float e0 = (1.0f/3.0f) * s1i * s1j0 - 0.5f * S2a;
    const float e1 = (1.0f/3.0f) * s1i * s1j1 - 0.5f * S2b;
    const float* g2 = s0 + 8;

    float l3[16];
    #pragma unroll
    for (int kk = 0; kk < 4; ++kk) {
        float s3a, s3b; unpack2(S30[kk], s3a, s3b);
        int k0 = 2 * kk;
        l3[k0]     = s3a + h * g2[j0*8 + k0]     + e0 * S1[k0];
        l3[k0 + 1] = s3b + h * g2[j0*8 + k0 + 1] + e0 * S1[k0 + 1];
    }
    #pragma unroll
    for (int kk = 0; kk < 4; ++kk) {
        float s3a, s3b; unpack2(S31[kk], s3a, s3b);
        int k0 = 2 * kk;
        l3[8 + k0]     = s3a + h * g2[(j0+1)*8 + k0]     + e1 * S1[k0];
        l3[8 + k0 + 1] = s3b + h * g2[(j0+1)*8 + k0 + 1] + e1 * S1[k0 + 1];
    }

    float* o3 = ob + 72 + 16 * lane;
    #pragma unroll
    for (int v = 0; v < 4; ++v)
        *reinterpret_cast<float4*>(o3 + 4 * v) =
            make_float4(l3[4*v], l3[4*v+1], l3[4*v+2], l3[4*v+3]);
}

extern "C" void kernel_launch(void* const* d_in, const int* in_sizes, int n_in,
                              void* d_out, int out_size)
{
    const float* x = (const float*)d_in[0];
    float* out = (float*)d_out;
    const int B = in_sizes[0] / (L_PATH * D_CH);   // 2048
    const int blocks = B / 2;                      // 2 batch elements per block
    logsig_kernel<<<blocks, 256>>>(x, out, B);
}